// round 16
// baseline (speedup 1.0000x reference)
#include <cuda_runtime.h>
#include <cuda_bf16.h>
#include <math.h>
#include <stdint.h>

#define NNODES 512
#define NEDGES 16384
#define LPN 20
#define TT 60
#define DD 128
#define H3 384
#define NGRU 21
#define GI_PER_G (NNODES*TT*H3)
#define LN_EPS 1e-5f

__device__ float g_GI[(size_t)NGRU * GI_PER_G];
__device__ float g_H[NGRU * NNODES * DD];
__device__ float g_cat[5 * NNODES * DD];
__device__ float g_bufA[NNODES * DD];
__device__ float g_bufB[NNODES * DD];
__device__ float g_bufC[NNODES * DD];
__device__ int   g_deg[NNODES];
__device__ float g_dinv[NNODES];
__device__ float g_logits[NNODES * 2];
__device__ uint32_t g_WHI[NGRU * H3 * 64];
__device__ uint32_t g_WLO[NGRU * H3 * 64];

__device__ __forceinline__ float sigmf_(float x) { return 1.f / (1.f + __expf(-x)); }
__device__ __forceinline__ float tanhf_(float x) {
    x = fminf(fmaxf(x, -15.f), 15.f);
    float e = __expf(2.f * x);
    return (e - 1.f) / (e + 1.f);
}

__device__ __forceinline__ void mma_bf16(float* d, const uint32_t* a, uint32_t b0, uint32_t b1) {
    asm volatile("mma.sync.aligned.m16n8k16.row.col.f32.bf16.bf16.f32 "
                 "{%0,%1,%2,%3}, {%4,%5,%6,%7}, {%8,%9}, {%0,%1,%2,%3};"
                 : "+f"(d[0]), "+f"(d[1]), "+f"(d[2]), "+f"(d[3])
                 : "r"(a[0]), "r"(a[1]), "r"(a[2]), "r"(a[3]), "r"(b0), "r"(b1));
}
__device__ __forceinline__ void ldsm_x4(uint32_t* r, uint32_t addr) {
    asm volatile("ldmatrix.sync.aligned.m8n8.x4.shared.b16 {%0,%1,%2,%3}, [%4];"
                 : "=r"(r[0]), "=r"(r[1]), "=r"(r[2]), "=r"(r[3]) : "r"(addr));
}
__device__ __forceinline__ uint32_t sm_addr(const void* p) {
    return (uint32_t)__cvta_generic_to_shared(p);
}
__device__ __forceinline__ void split2(float x, float y, uint32_t& hi, uint32_t& lo) {
    __nv_bfloat16 hx = __float2bfloat16(x);
    __nv_bfloat16 hy = __float2bfloat16(y);
    float rx = x - __bfloat162float(hx);
    float ry = y - __bfloat162float(hy);
    __nv_bfloat16 lx = __float2bfloat16(rx);
    __nv_bfloat16 ly = __float2bfloat16(ry);
    hi = ((uint32_t)__bfloat16_as_ushort(hy) << 16) | (uint32_t)__bfloat16_as_ushort(hx);
    lo = ((uint32_t)__bfloat16_as_ushort(ly) << 16) | (uint32_t)__bfloat16_as_ushort(lx);
}

// ---------------- prepass: split all Wih into bf16 hi/lo ----------------
__global__ void wsplit_kernel(const float* __restrict__ Wih_lp,
                              const float* __restrict__ Wih_ns)
{
    int idx = blockIdx.x * 256 + threadIdx.x;
    if (idx >= NGRU * H3 * 64) return;
    int g = idx / (H3 * 64);
    int rem = idx - g * H3 * 64;
    int n = rem >> 6, j = rem & 63;
    const float* W = (g < LPN) ? (Wih_lp + (size_t)g * H3 * DD) : Wih_ns;
    float2 v = *reinterpret_cast<const float2*>(W + (size_t)n * DD + 2 * j);
    uint32_t hi, lo;
    split2(v.x, v.y, hi, lo);
    g_WHI[idx] = hi;
    g_WLO[idx] = lo;
}

// ---------------- Phase 1 (bf16x3 MMA + ldmatrix): gi = x @ Wih^T + bih ----
// NOTE: bhh for r/z gates (cols < 256) is folded into the bias here.
#define PSTR 68
#define GI_SMEM ((2*64*PSTR + 2*128*PSTR) * 4)
__global__ __launch_bounds__(256, 2) void gi_bf16_kernel(
    const float* __restrict__ x_lp, const float* __restrict__ x_ns,
    const float* __restrict__ bih_lp, const float* __restrict__ bih_ns,
    const float* __restrict__ bhh_lp, const float* __restrict__ bhh_ns)
{
    extern __shared__ uint32_t su[];
    uint32_t* AHI = su;
    uint32_t* ALO = su + 64 * PSTR;
    uint32_t* BHI = su + 2 * 64 * PSTR;
    uint32_t* BLO = su + 2 * 64 * PSTR + 128 * PSTR;
    const int g = blockIdx.y;
    const int mbase = blockIdx.x * 64;
    const int tid = threadIdx.x;

    const float* bi  = (g < LPN) ? (bih_lp + g * H3) : bih_ns;
    const float* bhh = (g < LPN) ? (bhh_lp + g * H3) : bhh_ns;
    const float* xp  = (g < LPN) ? x_lp : x_ns;

    for (int idx = tid; idx < 64 * 64; idx += 256) {
        int r = idx >> 6, j = idx & 63;
        int row = mbase + r;
        size_t off;
        if (g < LPN) {
            int n = row / TT, t = row - n * TT;
            off = (size_t)n * (LPN * TT * DD) + (size_t)g * (TT * DD) + (size_t)t * DD;
        } else off = (size_t)row * DD;
        float2 v = *reinterpret_cast<const float2*>(xp + off + 2 * j);
        uint32_t hi, lo;
        split2(v.x, v.y, hi, lo);
        AHI[r * PSTR + j] = hi;
        ALO[r * PSTR + j] = lo;
    }

    const int wid = tid >> 5, lane = tid & 31;
    const int wm = wid & 1, wn = wid >> 1;
    const int grp = lane >> 2, tig = lane & 3;
    const int l7 = lane & 7, l8 = (lane >> 3) & 1, l16 = (lane >> 4) & 1;

    uint32_t aAhi[2], aAlo[2];
    #pragma unroll
    for (int mt = 0; mt < 2; mt++) {
        int row = wm * 32 + mt * 16 + l7 + l8 * 8;
        int word = l16 * 4;
        aAhi[mt] = sm_addr(AHI + row * PSTR + word);
        aAlo[mt] = sm_addr(ALO + row * PSTR + word);
    }
    uint32_t aBhi[2], aBlo[2];
    #pragma unroll
    for (int p = 0; p < 2; p++) {
        int col = wn * 32 + p * 16 + l7 + l16 * 8;
        int word = l8 * 4;
        aBhi[p] = sm_addr(BHI + col * PSTR + word);
        aBlo[p] = sm_addr(BLO + col * PSTR + word);
    }

    float* outp = g_GI + (size_t)g * GI_PER_G;
    const uint32_t* wsrc_hi = g_WHI + (size_t)g * H3 * 64;
    const uint32_t* wsrc_lo = g_WLO + (size_t)g * H3 * 64;

    for (int nb = 0; nb < 3; nb++) {
        const int nbase = nb * 128;
        for (int idx = tid; idx < 128 * 64; idx += 256) {
            int r = idx >> 6, j = idx & 63;
            BHI[r * PSTR + j] = wsrc_hi[(size_t)(nbase + r) * 64 + j];
            BLO[r * PSTR + j] = wsrc_lo[(size_t)(nbase + r) * 64 + j];
        }
        __syncthreads();

        float acc[2][4][4];
        #pragma unroll
        for (int mt = 0; mt < 2; mt++)
            #pragma unroll
            for (int nt = 0; nt < 4; nt++)
                #pragma unroll
                for (int q = 0; q < 4; q++) acc[mt][nt][q] = 0.f;

        #pragma unroll
        for (int kt = 0; kt < 8; kt++) {
            const uint32_t ko = kt * 32;
            uint32_t ah[2][4], al[2][4], bh[2][4], bl[2][4];
            #pragma unroll
            for (int mt = 0; mt < 2; mt++) {
                ldsm_x4(ah[mt], aAhi[mt] + ko);
                ldsm_x4(al[mt], aAlo[mt] + ko);
            }
            #pragma unroll
            for (int p = 0; p < 2; p++) {
                ldsm_x4(bh[p], aBhi[p] + ko);
                ldsm_x4(bl[p], aBlo[p] + ko);
            }
            #pragma unroll
            for (int p = 0; p < 2; p++)
                #pragma unroll
                for (int half = 0; half < 2; half++) {
                    int nt = 2 * p + half;
                    uint32_t b0h = bh[p][half * 2], b1h = bh[p][half * 2 + 1];
                    uint32_t b0l = bl[p][half * 2], b1l = bl[p][half * 2 + 1];
                    #pragma unroll
                    for (int mt = 0; mt < 2; mt++) {
                        mma_bf16(acc[mt][nt], ah[mt], b0h, b1h);
                        mma_bf16(acc[mt][nt], ah[mt], b0l, b1l);
                        mma_bf16(acc[mt][nt], al[mt], b0h, b1h);
                    }
                }
        }

        #pragma unroll
        for (int nt = 0; nt < 4; nt++) {
            int cg = nbase + wn * 32 + nt * 8 + tig * 2;
            float b0 = bi[cg]     + ((cg < 256)     ? bhh[cg]     : 0.f);
            float b1 = bi[cg + 1] + ((cg + 1 < 256) ? bhh[cg + 1] : 0.f);
            #pragma unroll
            for (int mt = 0; mt < 2; mt++) {
                int r0 = mbase + wm * 32 + mt * 16 + grp;
                *reinterpret_cast<float2*>(outp + (size_t)r0 * H3 + cg) =
                    make_float2(acc[mt][nt][0] + b0, acc[mt][nt][1] + b1);
                *reinterpret_cast<float2*>(outp + (size_t)(r0 + 8) * H3 + cg) =
                    make_float2(acc[mt][nt][2] + b0, acc[mt][nt][3] + b1);
            }
        }
        __syncthreads();
    }
}

// ---------------- Phase 2 (bf16x3 MMA recurrence, 64 nodes/CTA, 512 thr) ---
// grid (8, 21). 16 warps; warp w owns hidden cols [w*8, w*8+8) of all 3 gates.
// h in smem (hi/lo, XOR-swizzled); gi prefetched at loop top; bhh_r/z already
// folded into GI by gi_bf16_kernel (only bhh_n applied here, inside r*(.)).
// smem word of (row, j): row*64 + (((j>>2) ^ (row&7)) << 2) + (j&3)
#define GRU_SMEM ((2*384*64 + 2*64*64) * 4)

__global__ __launch_bounds__(512, 1) void gru_mma_kernel(
    const float* __restrict__ Whh_lp, const float* __restrict__ bhh_lp,
    const float* __restrict__ Whh_ns, const float* __restrict__ bhh_ns)
{
    extern __shared__ uint32_t su[];
    uint32_t* WHI = su;
    uint32_t* WLO = su + 384 * 64;
    uint32_t* HHI = su + 2 * 384 * 64;
    uint32_t* HLO = su + 2 * 384 * 64 + 64 * 64;
    const int g = blockIdx.y;
    const int base = blockIdx.x * 64;
    const int tid = threadIdx.x;

    const float* Wp = (g < LPN) ? (Whh_lp + (size_t)g * H3 * DD) : Whh_ns;
    const float* bh = (g < LPN) ? (bhh_lp + g * H3) : bhh_ns;

    for (int idx = tid; idx < 384 * 64; idx += 512) {
        int n = idx >> 6, j = idx & 63;
        float2 wv = *reinterpret_cast<const float2*>(Wp + (size_t)n * DD + 2 * j);
        uint32_t hi, lo;
        split2(wv.x, wv.y, hi, lo);
        int pj = ((((j >> 2) ^ (n & 7)) << 2) | (j & 3));
        WHI[n * 64 + pj] = hi;
        WLO[n * 64 + pj] = lo;
    }
    for (int idx = tid; idx < 64 * 64; idx += 512) { HHI[idx] = 0u; HLO[idx] = 0u; }

    const int w = tid >> 5, lane = tid & 31;
    const int grp = lane >> 2, tig = lane & 3;
    const int l7 = lane & 7, l15 = lane & 15;
    const int lA = (lane >> 4) & 1;   // A word-group select
    const int lB = lane >> 3;         // B matrix index 0..3

    // only bhh_n survives here (r/z folded into GI)
    float bias_n[2];
    #pragma unroll
    for (int cl = 0; cl < 2; cl++)
        bias_n[cl] = bh[256 + w * 8 + tig * 2 + cl];

    uint32_t aHhi[4], aHlo[4];
    #pragma unroll
    for (int mt = 0; mt < 4; mt++) {
        int r = mt * 16 + l15;
        aHhi[mt] = sm_addr(HHI + r * 64);
        aHlo[mt] = sm_addr(HLO + r * 64);
    }
    uint32_t aWhi[3], aWlo[3];
    #pragma unroll
    for (int p = 0; p < 3; p++) {
        int r = p * 128 + w * 8 + l7;
        aWhi[p] = sm_addr(WHI + r * 64);
        aWlo[p] = sm_addr(WLO + r * 64);
    }

    float hreg[4][4];
    #pragma unroll
    for (int mt = 0; mt < 4; mt++)
        #pragma unroll
        for (int q = 0; q < 4; q++) hreg[mt][q] = 0.f;

    __syncthreads();

    const float* gib = g_GI + (size_t)g * GI_PER_G;

    for (int t = 0; t < TT; t++) {
        // prefetch gi for this lane's 8 rows x 3 gates (hidden under MMA phase)
        float2 gi2[8][3];
        #pragma unroll
        for (int mi = 0; mi < 8; mi++) {
            int node = base + (mi >> 1) * 16 + (mi & 1) * 8 + grp;
            const float* rowp = gib + ((size_t)node * TT + t) * H3 + w * 8 + tig * 2;
            gi2[mi][0] = *reinterpret_cast<const float2*>(rowp);
            gi2[mi][1] = *reinterpret_cast<const float2*>(rowp + 128);
            gi2[mi][2] = *reinterpret_cast<const float2*>(rowp + 256);
        }

        float acc[4][3][4];
        #pragma unroll
        for (int mt = 0; mt < 4; mt++)
            #pragma unroll
            for (int p = 0; p < 3; p++)
                #pragma unroll
                for (int q = 0; q < 4; q++) acc[mt][p][q] = 0.f;

        #pragma unroll
        for (int kp = 0; kp < 4; kp++) {
            uint32_t offB = ((uint32_t)((lB + 4 * kp) ^ l7)) << 4;
            uint32_t wh[3][4], wl[3][4];
            #pragma unroll
            for (int p = 0; p < 3; p++) {
                ldsm_x4(wh[p], aWhi[p] + offB);
                ldsm_x4(wl[p], aWlo[p] + offB);
            }
            #pragma unroll
            for (int sub = 0; sub < 2; sub++) {
                int kt = 2 * kp + sub;
                uint32_t offA = ((uint32_t)((lA + 2 * kt) ^ l7)) << 4;
                uint32_t ah[4][4], al[4][4];
                #pragma unroll
                for (int mt = 0; mt < 4; mt++) {
                    ldsm_x4(ah[mt], aHhi[mt] + offA);
                    ldsm_x4(al[mt], aHlo[mt] + offA);
                }
                #pragma unroll
                for (int p = 0; p < 3; p++) {
                    uint32_t b0h = wh[p][sub * 2], b1h = wh[p][sub * 2 + 1];
                    uint32_t b0l = wl[p][sub * 2], b1l = wl[p][sub * 2 + 1];
                    #pragma unroll
                    for (int mt = 0; mt < 4; mt++) {
                        mma_bf16(acc[mt][p], ah[mt], b0h, b1h);
                        mma_bf16(acc[mt][p], ah[mt], b0l, b1l);
                        mma_bf16(acc[mt][p], al[mt], b0h, b1h);
                    }
                }
            }
        }
        __syncthreads();

        #pragma unroll
        for (int mt = 0; mt < 4; mt++)
            #pragma unroll
            for (int rh = 0; rh < 2; rh++) {
                int mi = mt * 2 + rh;
                #pragma unroll
                for (int cl = 0; cl < 2; cl++) {
                    int q = rh * 2 + cl;
                    float gi_r = cl ? gi2[mi][0].y : gi2[mi][0].x;
                    float gi_z = cl ? gi2[mi][1].y : gi2[mi][1].x;
                    float gi_n = cl ? gi2[mi][2].y : gi2[mi][2].x;
                    float r = sigmf_(gi_r + acc[mt][0][q]);
                    float z = sigmf_(gi_z + acc[mt][1][q]);
                    float nn = tanhf_(gi_n + r * (acc[mt][2][q] + bias_n[cl]));
                    hreg[mt][q] = (1.f - z) * nn + z * hreg[mt][q];
                }
            }
        // store h (bf16 hi/lo, swizzled) for next step's A operand
        #pragma unroll
        for (int mt = 0; mt < 4; mt++)
            #pragma unroll
            for (int rh = 0; rh < 2; rh++) {
                int row = mt * 16 + rh * 8 + grp;
                uint32_t hi, lo;
                split2(hreg[mt][rh * 2], hreg[mt][rh * 2 + 1], hi, lo);
                int pj = ((w ^ (row & 7)) << 2) | tig;
                HHI[row * 64 + pj] = hi;
                HLO[row * 64 + pj] = lo;
            }
        __syncthreads();
    }

    #pragma unroll
    for (int mt = 0; mt < 4; mt++)
        #pragma unroll
        for (int rh = 0; rh < 2; rh++) {
            int node = base + mt * 16 + rh * 8 + grp;
            float* op = g_H + ((size_t)g * NNODES + node) * DD + w * 8 + tig * 2;
            op[0] = hreg[mt][rh * 2];
            op[1] = hreg[mt][rh * 2 + 1];
        }
}

// ---------------- tail kernels ----------------
__global__ void gemm_tn_kernel(const float* __restrict__ A, int lda,
                               const float* __restrict__ B, int ldb,
                               const float* __restrict__ bias,
                               float* __restrict__ C, int ldc,
                               int M, int N, int K,
                               const float* __restrict__ aggbias,
                               float* __restrict__ aggout)
{
    __shared__ float As[32 * 32];
    __shared__ float Bs[32 * 33];
    const int rbase = blockIdx.x * 32;
    const int cbase = blockIdx.y * 32;
    const int tid = threadIdx.x;
    const int ty = tid >> 5, tx = tid & 31;

    float acc[4] = {0.f, 0.f, 0.f, 0.f};
    for (int kb = 0; kb < K; kb += 32) {
        #pragma unroll
        for (int i = 0; i < 4; i++) {
            int idx = tid + i * 256;
            int r = idx >> 5, kk = idx & 31;
            As[r * 32 + kk] = A[(size_t)(rbase + r) * lda + kb + kk];
            Bs[r * 33 + kk] = (cbase + r < N) ? B[(size_t)(cbase + r) * ldb + kb + kk] : 0.f;
        }
        __syncthreads();
        #pragma unroll
        for (int kk = 0; kk < 32; kk++) {
            float bv = Bs[tx * 33 + kk];
            #pragma unroll
            for (int i = 0; i < 4; i++)
                acc[i] += As[(ty + 8 * i) * 32 + kk] * bv;
        }
        __syncthreads();
    }
    if (cbase + tx < N) {
        float bb = bias ? bias[cbase + tx] : 0.f;
        #pragma unroll
        for (int i = 0; i < 4; i++) {
            int row = rbase + ty + 8 * i;
            C[(size_t)row * ldc + cbase + tx] = acc[i] + bb;
            if (aggout) {
                float di = g_dinv[row];
                aggout[(size_t)row * ldc + cbase + tx] =
                    aggbias[cbase + tx] + di * di * acc[i];
            }
        }
    }
}

__global__ void build_cat_kernel(const float* __restrict__ x_pdt,
                                 const float* __restrict__ x_ref,
                                 const float* __restrict__ x_def)
{
    int i = blockIdx.x * 256 + threadIdx.x;
    g_cat[i] = x_pdt[i];
    g_cat[NNODES * DD + i] = x_ref[i];
    g_cat[2 * NNODES * DD + i] = x_def[i];
    g_cat[4 * NNODES * DD + i] = g_H[(size_t)LPN * NNODES * DD + i];
}

__global__ void deg_init_kernel() {
    int i = blockIdx.x * 256 + threadIdx.x;
    if (i < NNODES) g_deg[i] = 1;
}
__global__ void deg_edge_kernel(const int* __restrict__ ei) {
    int e = blockIdx.x * 256 + threadIdx.x;
    if (e < NEDGES) atomicAdd(&g_deg[ei[NEDGES + e]], 1);
}
__global__ void dinv_kernel() {
    int i = blockIdx.x * 256 + threadIdx.x;
    if (i < NNODES) g_dinv[i] = rsqrtf((float)g_deg[i]);
}
__global__ void agg_edge_kernel(const float* __restrict__ xw,
                                const int* __restrict__ ei,
                                float* __restrict__ out)
{
    int i = blockIdx.x * 256 + threadIdx.x;
    int e = i >> 7, d = i & 127;
    int s = ei[e], t = ei[NEDGES + e];
    atomicAdd(&out[t * 128 + d], xw[s * 128 + d] * g_dinv[s] * g_dinv[t]);
}
__global__ void relu_ln_kernel(const float* __restrict__ in,
                               const float* __restrict__ gam,
                               const float* __restrict__ bet,
                               float* __restrict__ out)
{
    int row = blockIdx.x, d = threadIdx.x;
    float v = fmaxf(in[row * 128 + d], 0.f);
    float s = v, sq = v * v;
    #pragma unroll
    for (int o = 16; o > 0; o >>= 1) {
        s  += __shfl_xor_sync(0xffffffffu, s, o);
        sq += __shfl_xor_sync(0xffffffffu, sq, o);
    }
    __shared__ float ss[4], ssq[4];
    int w = d >> 5, l = d & 31;
    if (l == 0) { ss[w] = s; ssq[w] = sq; }
    __syncthreads();
    float st = ss[0] + ss[1] + ss[2] + ss[3];
    float sqt = ssq[0] + ssq[1] + ssq[2] + ssq[3];
    float m = st * (1.f / 128.f);
    float var = sqt * (1.f / 128.f) - m * m;
    out[row * 128 + d] = (v - m) * rsqrtf(var + LN_EPS) * gam[d] + bet[d];
}
__global__ void relu_kernel(const float* __restrict__ in, float* __restrict__ out) {
    int i = blockIdx.x * 256 + threadIdx.x;
    if (i < NNODES * DD) out[i] = fmaxf(in[i], 0.f);
}
__global__ void logsoftmax_kernel(float* __restrict__ out) {
    int i = blockIdx.x * 256 + threadIdx.x;
    if (i < NNODES) {
        float a = g_logits[2 * i], b = g_logits[2 * i + 1];
        float m = fmaxf(a, b);
        float lse = m + logf(expf(a - m) + expf(b - m));
        out[2 * i] = a - lse;
        out[2 * i + 1] = b - lse;
    }
}

extern "C" void kernel_launch(void* const* d_in, const int* in_sizes, int n_in,
                              void* d_out, int out_size)
{
    const float* x_lp    = (const float*)d_in[0];
    const float* x_ns    = (const float*)d_in[1];
    const float* x_ref   = (const float*)d_in[2];
    const float* x_def   = (const float*)d_in[3];
    const float* x_pdt   = (const float*)d_in[4];
    const int*   edge    = (const int*)  d_in[5];
    const float* Wih_lp  = (const float*)d_in[6];
    const float* Whh_lp  = (const float*)d_in[7];
    const float* bih_lp  = (const float*)d_in[8];
    const float* bhh_lp  = (const float*)d_in[9];
    const float* lp_fc_W = (const float*)d_in[10];
    const float* lp_fc_b = (const float*)d_in[11];
    const float* Wih_ns  = (const float*)d_in[12];
    const float* Whh_ns  = (const float*)d_in[13];
    const float* bih_ns  = (const float*)d_in[14];
    const float* bhh_ns  = (const float*)d_in[15];
    const float* all_fc_W = (const float*)d_in[16];
    const float* all_fc_b = (const float*)d_in[17];
    const float* convW[3] = {(const float*)d_in[18], (const float*)d_in[20], (const float*)d_in[22]};
    const float* convB[3] = {(const float*)d_in[19], (const float*)d_in[21], (const float*)d_in[23]};
    const float* lnG[2] = {(const float*)d_in[24], (const float*)d_in[26]};
    const float* lnB[2] = {(const float*)d_in[25], (const float*)d_in[27]};
    const float* mp1_W = (const float*)d_in[28];
    const float* mp1_b = (const float*)d_in[29];
    const float* mp2_W = (const float*)d_in[30];
    const float* mp2_b = (const float*)d_in[31];
    float* out = (float*)d_out;
    (void)in_sizes; (void)n_in; (void)out_size;

    float *H, *cat, *bufA, *bufB, *bufC, *logits;
    cudaGetSymbolAddress((void**)&H, g_H);
    cudaGetSymbolAddress((void**)&cat, g_cat);
    cudaGetSymbolAddress((void**)&bufA, g_bufA);
    cudaGetSymbolAddress((void**)&bufB, g_bufB);
    cudaGetSymbolAddress((void**)&bufC, g_bufC);
    cudaGetSymbolAddress((void**)&logits, g_logits);

    cudaFuncSetAttribute(gi_bf16_kernel, cudaFuncAttributeMaxDynamicSharedMemorySize, GI_SMEM);
    cudaFuncSetAttribute(gru_mma_kernel, cudaFuncAttributeMaxDynamicSharedMemorySize, GRU_SMEM);

    // order: capture slot (idx 3) lands on gru_mma_kernel
    wsplit_kernel<<<(NGRU * H3 * 64 + 255) / 256, 256>>>(Wih_lp, Wih_ns);
    gi_bf16_kernel<<<dim3(480, NGRU), 256, GI_SMEM>>>(x_lp, x_ns, bih_lp, bih_ns, bhh_lp, bhh_ns);
    deg_init_kernel<<<2, 256>>>();
    gru_mma_kernel<<<dim3(8, NGRU), 512, GRU_SMEM>>>(Whh_lp, bhh_lp, Whh_ns, bhh_ns);
    deg_edge_kernel<<<NEDGES / 256, 256>>>(edge);
    dinv_kernel<<<2, 256>>>();

    gemm_tn_kernel<<<dim3(16, 4), 256>>>(H, LPN * DD, lp_fc_W, LPN * DD, lp_fc_b,
                                         cat + 3 * NNODES * DD, DD, NNODES, DD, LPN * DD,
                                         nullptr, nullptr);
    build_cat_kernel<<<256, 256>>>(x_pdt, x_ref, x_def);
    gemm_tn_kernel<<<dim3(16, 4), 256>>>(cat, 5 * DD, all_fc_W, 5 * DD, all_fc_b,
                                         bufA, DD, NNODES, DD, 5 * DD, nullptr, nullptr);

    // conv0
    gemm_tn_kernel<<<dim3(16, 4), 256>>>(bufA, DD, convW[0], DD, nullptr, bufB, DD,
                                         NNODES, DD, DD, convB[0], bufC);
    agg_edge_kernel<<<NEDGES * DD / 256, 256>>>(bufB, edge, bufC);
    relu_ln_kernel<<<NNODES, 128>>>(bufC, lnG[0], lnB[0], bufA);
    // conv1
    gemm_tn_kernel<<<dim3(16, 4), 256>>>(bufA, DD, convW[1], DD, nullptr, bufB, DD,
                                         NNODES, DD, DD, convB[1], bufC);
    agg_edge_kernel<<<NEDGES * DD / 256, 256>>>(bufB, edge, bufC);
    relu_ln_kernel<<<NNODES, 128>>>(bufC, lnG[1], lnB[1], bufA);
    // conv2 -> emb straight to d_out[0:65536]
    gemm_tn_kernel<<<dim3(16, 4), 256>>>(bufA, DD, convW[2], DD, nullptr, bufB, DD,
                                         NNODES, DD, DD, convB[2], out);
    agg_edge_kernel<<<NEDGES * DD / 256, 256>>>(bufB, edge, out);
    relu_kernel<<<256, 256>>>(out, bufA);
    // mp1, mp2
    gemm_tn_kernel<<<dim3(16, 4), 256>>>(bufA, DD, mp1_W, DD, mp1_b, bufB, DD,
                                         NNODES, DD, DD, nullptr, nullptr);
    gemm_tn_kernel<<<dim3(16, 1), 256>>>(bufB, DD, mp2_W, DD, mp2_b, logits, 2,
                                         NNODES, 2, DD, nullptr, nullptr);
    logsoftmax_kernel<<<2, 256>>>(out + NNODES * DD);
}

// round 17
// speedup vs baseline: 1.4696x; 1.4696x over previous
#include <cuda_runtime.h>
#include <cuda_fp16.h>
#include <math.h>
#include <stdint.h>

#define NNODES 512
#define NEDGES 16384
#define LPN 20
#define TT 60
#define DD 128
#define H3 384
#define NGRU 21
#define GI_PER_G (NNODES*TT*H3)
#define LN_EPS 1e-5f

__device__ __half g_GIh[(size_t)NGRU * GI_PER_G];      // gi in fp16 (495MB)
__device__ uint32_t g_WH[NGRU * H3 * 64];              // Wih as half2 words
__device__ float g_H[NGRU * NNODES * DD];
__device__ float g_cat[5 * NNODES * DD];
__device__ float g_bufA[NNODES * DD];
__device__ float g_bufB[NNODES * DD];
__device__ float g_bufC[NNODES * DD];
__device__ int   g_deg[NNODES];
__device__ float g_dinv[NNODES];
__device__ float g_logits[NNODES * 2];

__device__ __forceinline__ float sigmf_(float x) { return 1.f / (1.f + __expf(-x)); }
__device__ __forceinline__ float tanhf_(float x) {
    x = fminf(fmaxf(x, -15.f), 15.f);
    float e = __expf(2.f * x);
    return (e - 1.f) / (e + 1.f);
}

__device__ __forceinline__ void mma_f16(float* d, const uint32_t* a, uint32_t b0, uint32_t b1) {
    asm volatile("mma.sync.aligned.m16n8k16.row.col.f32.f16.f16.f32 "
                 "{%0,%1,%2,%3}, {%4,%5,%6,%7}, {%8,%9}, {%0,%1,%2,%3};"
                 : "+f"(d[0]), "+f"(d[1]), "+f"(d[2]), "+f"(d[3])
                 : "r"(a[0]), "r"(a[1]), "r"(a[2]), "r"(a[3]), "r"(b0), "r"(b1));
}
__device__ __forceinline__ void ldsm_x4(uint32_t* r, uint32_t addr) {
    asm volatile("ldmatrix.sync.aligned.m8n8.x4.shared.b16 {%0,%1,%2,%3}, [%4];"
                 : "=r"(r[0]), "=r"(r[1]), "=r"(r[2]), "=r"(r[3]) : "r"(addr));
}
__device__ __forceinline__ uint32_t sm_addr(const void* p) {
    return (uint32_t)__cvta_generic_to_shared(p);
}
__device__ __forceinline__ uint32_t pack_h2(float x, float y) {
    __half2 h = __floats2half2_rn(x, y);
    return *reinterpret_cast<uint32_t*>(&h);
}
__device__ __forceinline__ float2 unpack_h2(uint32_t u) {
    __half2 h = *reinterpret_cast<__half2*>(&u);
    return __half22float2(h);
}

// ---------------- prepass: convert all Wih to fp16 ----------------
__global__ void wsplit_kernel(const float* __restrict__ Wih_lp,
                              const float* __restrict__ Wih_ns)
{
    int idx = blockIdx.x * 256 + threadIdx.x;
    if (idx >= NGRU * H3 * 64) return;
    int g = idx / (H3 * 64);
    int rem = idx - g * H3 * 64;
    int n = rem >> 6, j = rem & 63;
    const float* W = (g < LPN) ? (Wih_lp + (size_t)g * H3 * DD) : Wih_ns;
    float2 v = *reinterpret_cast<const float2*>(W + (size_t)n * DD + 2 * j);
    g_WH[idx] = pack_h2(v.x, v.y);
}

// ---------------- Phase 1 (fp16 MMA): gi = x @ Wih^T + bih (+bhh r/z) ----
#define PSTR 68
#define GI_SMEM ((64*PSTR + 128*PSTR) * 4)
__global__ __launch_bounds__(256, 3) void gi_f16_kernel(
    const float* __restrict__ x_lp, const float* __restrict__ x_ns,
    const float* __restrict__ bih_lp, const float* __restrict__ bih_ns,
    const float* __restrict__ bhh_lp, const float* __restrict__ bhh_ns)
{
    extern __shared__ uint32_t su[];
    uint32_t* AH = su;                 // [64][68] half2 words
    uint32_t* BH = su + 64 * PSTR;     // [128][68]
    const int g = blockIdx.y;
    const int mbase = blockIdx.x * 64;
    const int tid = threadIdx.x;

    const float* bi  = (g < LPN) ? (bih_lp + g * H3) : bih_ns;
    const float* bhh = (g < LPN) ? (bhh_lp + g * H3) : bhh_ns;
    const float* xp  = (g < LPN) ? x_lp : x_ns;

    for (int idx = tid; idx < 64 * 64; idx += 256) {
        int r = idx >> 6, j = idx & 63;
        int row = mbase + r;
        size_t off;
        if (g < LPN) {
            int n = row / TT, t = row - n * TT;
            off = (size_t)n * (LPN * TT * DD) + (size_t)g * (TT * DD) + (size_t)t * DD;
        } else off = (size_t)row * DD;
        float2 v = *reinterpret_cast<const float2*>(xp + off + 2 * j);
        AH[r * PSTR + j] = pack_h2(v.x, v.y);
    }

    const int wid = tid >> 5, lane = tid & 31;
    const int wm = wid & 1, wn = wid >> 1;
    const int grp = lane >> 2, tig = lane & 3;
    const int l7 = lane & 7, l8 = (lane >> 3) & 1, l16 = (lane >> 4) & 1;

    uint32_t aA[2];
    #pragma unroll
    for (int mt = 0; mt < 2; mt++) {
        int row = wm * 32 + mt * 16 + l7 + l8 * 8;
        aA[mt] = sm_addr(AH + row * PSTR + l16 * 4);
    }
    uint32_t aB[2];
    #pragma unroll
    for (int p = 0; p < 2; p++) {
        int col = wn * 32 + p * 16 + l7 + l16 * 8;
        aB[p] = sm_addr(BH + col * PSTR + l8 * 4);
    }

    __half* outp = g_GIh + (size_t)g * GI_PER_G;
    const uint32_t* wsrc = g_WH + (size_t)g * H3 * 64;

    for (int nb = 0; nb < 3; nb++) {
        const int nbase = nb * 128;
        for (int idx = tid; idx < 128 * 64; idx += 256) {
            int r = idx >> 6, j = idx & 63;
            BH[r * PSTR + j] = wsrc[(size_t)(nbase + r) * 64 + j];
        }
        __syncthreads();

        float acc[2][4][4];
        #pragma unroll
        for (int mt = 0; mt < 2; mt++)
            #pragma unroll
            for (int nt = 0; nt < 4; nt++)
                #pragma unroll
                for (int q = 0; q < 4; q++) acc[mt][nt][q] = 0.f;

        #pragma unroll
        for (int kt = 0; kt < 8; kt++) {
            const uint32_t ko = kt * 32;
            uint32_t av[2][4], bv[2][4];
            #pragma unroll
            for (int mt = 0; mt < 2; mt++) ldsm_x4(av[mt], aA[mt] + ko);
            #pragma unroll
            for (int p = 0; p < 2; p++)  ldsm_x4(bv[p], aB[p] + ko);
            #pragma unroll
            for (int p = 0; p < 2; p++)
                #pragma unroll
                for (int half = 0; half < 2; half++) {
                    int nt = 2 * p + half;
                    #pragma unroll
                    for (int mt = 0; mt < 2; mt++)
                        mma_f16(acc[mt][nt], av[mt], bv[p][half * 2], bv[p][half * 2 + 1]);
                }
        }

        #pragma unroll
        for (int nt = 0; nt < 4; nt++) {
            int cg = nbase + wn * 32 + nt * 8 + tig * 2;
            float b0 = bi[cg]     + ((cg < 256)     ? bhh[cg]     : 0.f);
            float b1 = bi[cg + 1] + ((cg + 1 < 256) ? bhh[cg + 1] : 0.f);
            #pragma unroll
            for (int mt = 0; mt < 2; mt++) {
                int r0 = mbase + wm * 32 + mt * 16 + grp;
                *reinterpret_cast<uint32_t*>(outp + (size_t)r0 * H3 + cg) =
                    pack_h2(acc[mt][nt][0] + b0, acc[mt][nt][1] + b1);
                *reinterpret_cast<uint32_t*>(outp + (size_t)(r0 + 8) * H3 + cg) =
                    pack_h2(acc[mt][nt][2] + b0, acc[mt][nt][3] + b1);
            }
        }
        __syncthreads();
    }
}

// ---------------- Phase 2: fp16 GRU recurrence, 128 nodes/CTA, 1 wave -----
// grid (4, 21), 256 thr (8 warps). Warp w owns cols [w*16, w*16+16) of each
// gate. Whh fp16 [384][64] + h fp16 [128][64] in smem, XOR-swizzled:
//   word(row, j) at row*64 + (((j>>2) ^ (row&7)) << 2) + (j&3)
// Step is processed in two node-halves (rows 0-63, 64-127) with one barrier
// after each half's MMA-read phase (write/read race safety proven disjoint).
#define GRU_SMEM ((384*64 + 128*64) * 4)

__global__ __launch_bounds__(256, 1) void gru_mma_kernel(
    const float* __restrict__ Whh_lp, const float* __restrict__ bhh_lp,
    const float* __restrict__ Whh_ns, const float* __restrict__ bhh_ns)
{
    extern __shared__ uint32_t su[];
    uint32_t* WH = su;                 // [384][64] half2, swizzled
    uint32_t* HH = su + 384 * 64;      // [128][64] half2, swizzled
    const int g = blockIdx.y;
    const int base = blockIdx.x * 128;
    const int tid = threadIdx.x;

    const float* Wp = (g < LPN) ? (Whh_lp + (size_t)g * H3 * DD) : Whh_ns;
    const float* bh = (g < LPN) ? (bhh_lp + g * H3) : bhh_ns;

    for (int idx = tid; idx < 384 * 64; idx += 256) {
        int n = idx >> 6, j = idx & 63;
        float2 wv = *reinterpret_cast<const float2*>(Wp + (size_t)n * DD + 2 * j);
        int pj = ((((j >> 2) ^ (n & 7)) << 2) | (j & 3));
        WH[n * 64 + pj] = pack_h2(wv.x, wv.y);
    }
    for (int idx = tid; idx < 128 * 64; idx += 256) HH[idx] = 0u;

    const int w = tid >> 5, lane = tid & 31;
    const int grp = lane >> 2, tig = lane & 3;
    const int l7 = lane & 7, l15 = lane & 15;
    const int lA = (lane >> 4) & 1;
    const int lB = lane >> 3;

    // bhh_n only (r/z folded into GI)
    float bias_n[2][2];
    #pragma unroll
    for (int bt = 0; bt < 2; bt++)
        #pragma unroll
        for (int cl = 0; cl < 2; cl++)
            bias_n[bt][cl] = bh[256 + w * 16 + bt * 8 + tig * 2 + cl];

    uint32_t aH[8];
    #pragma unroll
    for (int mt = 0; mt < 8; mt++)
        aH[mt] = sm_addr(HH + (mt * 16 + l15) * 64);
    uint32_t aW[3][2];
    #pragma unroll
    for (int p = 0; p < 3; p++)
        #pragma unroll
        for (int bt = 0; bt < 2; bt++)
            aW[p][bt] = sm_addr(WH + (p * 128 + w * 16 + bt * 8 + l7) * 64);

    __syncthreads();

    const __half* gib = g_GIh + (size_t)g * GI_PER_G;

    for (int t = 0; t < TT; t++) {
        #pragma unroll
        for (int half = 0; half < 2; half++) {
            // gi prefetch for this half's 4 mt (hidden under MMA phase)
            uint32_t gi[4][2][3][2];  // [mtl][rh][gate][bt] half2 words
            #pragma unroll
            for (int mtl = 0; mtl < 4; mtl++) {
                int mt = half * 4 + mtl;
                #pragma unroll
                for (int rh = 0; rh < 2; rh++) {
                    int node = base + mt * 16 + rh * 8 + grp;
                    const __half* rp = gib + ((size_t)node * TT + t) * H3 + w * 16 + tig * 2;
                    #pragma unroll
                    for (int p = 0; p < 3; p++)
                        #pragma unroll
                        for (int bt = 0; bt < 2; bt++)
                            gi[mtl][rh][p][bt] =
                                *reinterpret_cast<const uint32_t*>(rp + p * 128 + bt * 8);
                }
            }

            float acc[4][6][4];
            #pragma unroll
            for (int mtl = 0; mtl < 4; mtl++)
                #pragma unroll
                for (int nt = 0; nt < 6; nt++)
                    #pragma unroll
                    for (int q = 0; q < 4; q++) acc[mtl][nt][q] = 0.f;

            #pragma unroll
            for (int kp = 0; kp < 4; kp++) {
                uint32_t offB = ((uint32_t)((lB + 4 * kp) ^ l7)) << 4;
                uint32_t bw[3][2][4];
                #pragma unroll
                for (int p = 0; p < 3; p++)
                    #pragma unroll
                    for (int bt = 0; bt < 2; bt++)
                        ldsm_x4(bw[p][bt], aW[p][bt] + offB);
                #pragma unroll
                for (int sub = 0; sub < 2; sub++) {
                    int kt = 2 * kp + sub;
                    uint32_t offA = ((uint32_t)((lA + 2 * kt) ^ l7)) << 4;
                    uint32_t ax[4][4];
                    #pragma unroll
                    for (int mtl = 0; mtl < 4; mtl++)
                        ldsm_x4(ax[mtl], aH[half * 4 + mtl] + offA);
                    #pragma unroll
                    for (int p = 0; p < 3; p++)
                        #pragma unroll
                        for (int bt = 0; bt < 2; bt++) {
                            uint32_t b0 = bw[p][bt][sub * 2], b1 = bw[p][bt][sub * 2 + 1];
                            #pragma unroll
                            for (int mtl = 0; mtl < 4; mtl++)
                                mma_f16(acc[mtl][p * 2 + bt], ax[mtl], b0, b1);
                        }
                }
            }
            __syncthreads();   // all warps' reads of old h done for this half

            // epilogue: gates + h update; write h (fp16, swizzled)
            #pragma unroll
            for (int mtl = 0; mtl < 4; mtl++) {
                int mt = half * 4 + mtl;
                #pragma unroll
                for (int rh = 0; rh < 2; rh++) {
                    int row = mt * 16 + rh * 8 + grp;
                    #pragma unroll
                    for (int bt = 0; bt < 2; bt++) {
                        int j = w * 8 + bt * 4 + tig;
                        int pj = ((((j >> 2) ^ (row & 7)) << 2) | (j & 3));
                        float2 hold = unpack_h2(HH[row * 64 + pj]);
                        float2 gr = unpack_h2(gi[mtl][rh][0][bt]);
                        float2 gz = unpack_h2(gi[mtl][rh][1][bt]);
                        float2 gn = unpack_h2(gi[mtl][rh][2][bt]);
                        float hn[2];
                        #pragma unroll
                        for (int cl = 0; cl < 2; cl++) {
                            int q = rh * 2 + cl;
                            float gi_r = cl ? gr.y : gr.x;
                            float gi_z = cl ? gz.y : gz.x;
                            float gi_n = cl ? gn.y : gn.x;
                            float r = sigmf_(gi_r + acc[mtl][0 + bt][q]);
                            float z = sigmf_(gi_z + acc[mtl][2 + bt][q]);
                            float nn = tanhf_(gi_n + r * (acc[mtl][4 + bt][q] + bias_n[bt][cl]));
                            float ho = cl ? hold.y : hold.x;
                            hn[cl] = (1.f - z) * nn + z * ho;
                        }
                        HH[row * 64 + pj] = pack_h2(hn[0], hn[1]);
                    }
                }
            }
        }
    }

    __syncthreads();
    // writeout final h -> g_H (fp32)
    for (int idx = tid; idx < 128 * 64; idx += 256) {
        int n = idx >> 6, j = idx & 63;
        int pj = ((((j >> 2) ^ (n & 7)) << 2) | (j & 3));
        float2 v = unpack_h2(HH[n * 64 + pj]);
        float* op = g_H + ((size_t)g * NNODES + base + n) * DD + 2 * j;
        op[0] = v.x;
        op[1] = v.y;
    }
}

// ---------------- tail kernels ----------------
__global__ void gemm_tn_kernel(const float* __restrict__ A, int lda,
                               const float* __restrict__ B, int ldb,
                               const float* __restrict__ bias,
                               float* __restrict__ C, int ldc,
                               int M, int N, int K,
                               const float* __restrict__ aggbias,
                               float* __restrict__ aggout)
{
    __shared__ float As[32 * 32];
    __shared__ float Bs[32 * 33];
    const int rbase = blockIdx.x * 32;
    const int cbase = blockIdx.y * 32;
    const int tid = threadIdx.x;
    const int ty = tid >> 5, tx = tid & 31;

    float acc[4] = {0.f, 0.f, 0.f, 0.f};
    for (int kb = 0; kb < K; kb += 32) {
        #pragma unroll
        for (int i = 0; i < 4; i++) {
            int idx = tid + i * 256;
            int r = idx >> 5, kk = idx & 31;
            As[r * 32 + kk] = A[(size_t)(rbase + r) * lda + kb + kk];
            Bs[r * 33 + kk] = (cbase + r < N) ? B[(size_t)(cbase + r) * ldb + kb + kk] : 0.f;
        }
        __syncthreads();
        #pragma unroll
        for (int kk = 0; kk < 32; kk++) {
            float bv = Bs[tx * 33 + kk];
            #pragma unroll
            for (int i = 0; i < 4; i++)
                acc[i] += As[(ty + 8 * i) * 32 + kk] * bv;
        }
        __syncthreads();
    }
    if (cbase + tx < N) {
        float bb = bias ? bias[cbase + tx] : 0.f;
        #pragma unroll
        for (int i = 0; i < 4; i++) {
            int row = rbase + ty + 8 * i;
            C[(size_t)row * ldc + cbase + tx] = acc[i] + bb;
            if (aggout) {
                float di = g_dinv[row];
                aggout[(size_t)row * ldc + cbase + tx] =
                    aggbias[cbase + tx] + di * di * acc[i];
            }
        }
    }
}

__global__ void build_cat_kernel(const float* __restrict__ x_pdt,
                                 const float* __restrict__ x_ref,
                                 const float* __restrict__ x_def)
{
    int i = blockIdx.x * 256 + threadIdx.x;
    g_cat[i] = x_pdt[i];
    g_cat[NNODES * DD + i] = x_ref[i];
    g_cat[2 * NNODES * DD + i] = x_def[i];
    g_cat[4 * NNODES * DD + i] = g_H[(size_t)LPN * NNODES * DD + i];
}

__global__ void deg_init_kernel() {
    int i = blockIdx.x * 256 + threadIdx.x;
    if (i < NNODES) g_deg[i] = 1;
}
__global__ void deg_edge_kernel(const int* __restrict__ ei) {
    int e = blockIdx.x * 256 + threadIdx.x;
    if (e < NEDGES) atomicAdd(&g_deg[ei[NEDGES + e]], 1);
}
__global__ void dinv_kernel() {
    int i = blockIdx.x * 256 + threadIdx.x;
    if (i < NNODES) g_dinv[i] = rsqrtf((float)g_deg[i]);
}
__global__ void agg_edge_kernel(const float* __restrict__ xw,
                                const int* __restrict__ ei,
                                float* __restrict__ out)
{
    int i = blockIdx.x * 256 + threadIdx.x;
    int e = i >> 7, d = i & 127;
    int s = ei[e], t = ei[NEDGES + e];
    atomicAdd(&out[t * 128 + d], xw[s * 128 + d] * g_dinv[s] * g_dinv[t]);
}
__global__ void relu_ln_kernel(const float* __restrict__ in,
                               const float* __restrict__ gam,
                               const float* __restrict__ bet,
                               float* __restrict__ out)
{
    int row = blockIdx.x, d = threadIdx.x;
    float v = fmaxf(in[row * 128 + d], 0.f);
    float s = v, sq = v * v;
    #pragma unroll
    for (int o = 16; o > 0; o >>= 1) {
        s  += __shfl_xor_sync(0xffffffffu, s, o);
        sq += __shfl_xor_sync(0xffffffffu, sq, o);
    }
    __shared__ float ss[4], ssq[4];
    int w = d >> 5, l = d & 31;
    if (l == 0) { ss[w] = s; ssq[w] = sq; }
    __syncthreads();
    float st = ss[0] + ss[1] + ss[2] + ss[3];
    float sqt = ssq[0] + ssq[1] + ssq[2] + ssq[3];
    float m = st * (1.f / 128.f);
    float var = sqt * (1.f / 128.f) - m * m;
    out[row * 128 + d] = (v - m) * rsqrtf(var + LN_EPS) * gam[d] + bet[d];
}
__global__ void relu_kernel(const float* __restrict__ in, float* __restrict__ out) {
    int i = blockIdx.x * 256 + threadIdx.x;
    if (i < NNODES * DD) out[i] = fmaxf(in[i], 0.f);
}
__global__ void logsoftmax_kernel(float* __restrict__ out) {
    int i = blockIdx.x * 256 + threadIdx.x;
    if (i < NNODES) {
        float a = g_logits[2 * i], b = g_logits[2 * i + 1];
        float m = fmaxf(a, b);
        float lse = m + logf(expf(a - m) + expf(b - m));
        out[2 * i] = a - lse;
        out[2 * i + 1] = b - lse;
    }
}

extern "C" void kernel_launch(void* const* d_in, const int* in_sizes, int n_in,
                              void* d_out, int out_size)
{
    const float* x_lp    = (const float*)d_in[0];
    const float* x_ns    = (const float*)d_in[1];
    const float* x_ref   = (const float*)d_in[2];
    const float* x_def   = (const float*)d_in[3];
    const float* x_pdt   = (const float*)d_in[4];
    const int*   edge    = (const int*)  d_in[5];
    const float* Wih_lp  = (const float*)d_in[6];
    const float* Whh_lp  = (const float*)d_in[7];
    const float* bih_lp  = (const float*)d_in[8];
    const float* bhh_lp  = (const float*)d_in[9];
    const float* lp_fc_W = (const float*)d_in[10];
    const float* lp_fc_b = (const float*)d_in[11];
    const float* Wih_ns  = (const float*)d_in[12];
    const float* Whh_ns  = (const float*)d_in[13];
    const float* bih_ns  = (const float*)d_in[14];
    const float* bhh_ns  = (const float*)d_in[15];
    const float* all_fc_W = (const float*)d_in[16];
    const float* all_fc_b = (const float*)d_in[17];
    const float* convW[3] = {(const float*)d_in[18], (const float*)d_in[20], (const float*)d_in[22]};
    const float* convB[3] = {(const float*)d_in[19], (const float*)d_in[21], (const float*)d_in[23]};
    const float* lnG[2] = {(const float*)d_in[24], (const float*)d_in[26]};
    const float* lnB[2] = {(const float*)d_in[25], (const float*)d_in[27]};
    const float* mp1_W = (const float*)d_in[28];
    const float* mp1_b = (const float*)d_in[29];
    const float* mp2_W = (const float*)d_in[30];
    const float* mp2_b = (const float*)d_in[31];
    float* out = (float*)d_out;
    (void)in_sizes; (void)n_in; (void)out_size;

    float *H, *cat, *bufA, *bufB, *bufC, *logits;
    cudaGetSymbolAddress((void**)&H, g_H);
    cudaGetSymbolAddress((void**)&cat, g_cat);
    cudaGetSymbolAddress((void**)&bufA, g_bufA);
    cudaGetSymbolAddress((void**)&bufB, g_bufB);
    cudaGetSymbolAddress((void**)&bufC, g_bufC);
    cudaGetSymbolAddress((void**)&logits, g_logits);

    cudaFuncSetAttribute(gi_f16_kernel, cudaFuncAttributeMaxDynamicSharedMemorySize, GI_SMEM);
    cudaFuncSetAttribute(gru_mma_kernel, cudaFuncAttributeMaxDynamicSharedMemorySize, GRU_SMEM);

    // order: capture slot (idx 3) lands on gru_mma_kernel
    wsplit_kernel<<<(NGRU * H3 * 64 + 255) / 256, 256>>>(Wih_lp, Wih_ns);
    gi_f16_kernel<<<dim3(480, NGRU), 256, GI_SMEM>>>(x_lp, x_ns, bih_lp, bih_ns, bhh_lp, bhh_ns);
    deg_init_kernel<<<2, 256>>>();
    gru_mma_kernel<<<dim3(4, NGRU), 256, GRU_SMEM>>>(Whh_lp, bhh_lp, Whh_ns, bhh_ns);
    deg_edge_kernel<<<NEDGES / 256, 256>>>(edge);
    dinv_kernel<<<2, 256>>>();

    gemm_tn_kernel<<<dim3(16, 4), 256>>>(H, LPN * DD, lp_fc_W, LPN * DD, lp_fc_b,
                                         cat + 3 * NNODES * DD, DD, NNODES, DD, LPN * DD,
                                         nullptr, nullptr);
    build_cat_kernel<<<256, 256>>>(x_pdt, x_ref, x_def);
    gemm_tn_kernel<<<dim3(16, 4), 256>>>(cat, 5 * DD, all_fc_W, 5 * DD, all_fc_b,
                                         bufA, DD, NNODES, DD, 5 * DD, nullptr, nullptr);

    // conv0
    gemm_tn_kernel<<<dim3(16, 4), 256>>>(bufA, DD, convW[0], DD, nullptr, bufB, DD,
                                         NNODES, DD, DD, convB[0], bufC);
    agg_edge_kernel<<<NEDGES * DD / 256, 256>>>(bufB, edge, bufC);
    relu_ln_kernel<<<NNODES, 128>>>(bufC, lnG[0], lnB[0], bufA);
    // conv1
    gemm_tn_kernel<<<dim3(16, 4), 256>>>(bufA, DD, convW[1], DD, nullptr, bufB, DD,
                                         NNODES, DD, DD, convB[1], bufC);
    agg_edge_kernel<<<NEDGES * DD / 256, 256>>>(bufB, edge, bufC);
    relu_ln_kernel<<<NNODES, 128>>>(bufC, lnG[1], lnB[1], bufA);
    // conv2 -> emb straight to d_out[0:65536]
    gemm_tn_kernel<<<dim3(16, 4), 256>>>(bufA, DD, convW[2], DD, nullptr, bufB, DD,
                                         NNODES, DD, DD, convB[2], out);
    agg_edge_kernel<<<NEDGES * DD / 256, 256>>>(bufB, edge, out);
    relu_kernel<<<256, 256>>>(out, bufA);
    // mp1, mp2
    gemm_tn_kernel<<<dim3(16, 4), 256>>>(bufA, DD, mp1_W, DD, mp1_b, bufB, DD,
                                         NNODES, DD, DD, nullptr, nullptr);
    gemm_tn_kernel<<<dim3(16, 1), 256>>>(bufB, DD, mp2_W, DD, mp2_b, logits, 2,
                                         NNODES, 2, DD, nullptr, nullptr);
    logsoftmax_kernel<<<2, 256>>>(out + NNODES * DD);
}